// round 11
// baseline (speedup 1.0000x reference)
#include <cuda.h>
#include <cuda_runtime.h>
#include <cstdint>

// Equivariant linear: segments (u,i) = (64,1),(32,3),(16,5); in==out dim 240.
// R10 orchestration + dup-free inner loops:
//  seg1: K-pair (u-pair-major w layout), zero operand movs.
//  seg2: i-pair with split accumulators, w-dups hoisted across rows.

typedef unsigned long long u64;

__device__ __forceinline__ u64 fma2(u64 a, u64 b, u64 c) {
    u64 d;
    asm("fma.rn.f32x2 %0, %1, %2, %3;" : "=l"(d) : "l"(a), "l"(b), "l"(c));
    return d;
}
__device__ __forceinline__ u64 dup2(float x) {
    u64 d;
    asm("mov.b64 %0, {%1, %2};" : "=l"(d) : "f"(x), "f"(x));
    return d;
}
__device__ __forceinline__ float hsum2(u64 v) {
    float a, b;
    asm("mov.b64 {%0, %1}, %2;" : "=f"(a), "=f"(b) : "l"(v));
    return a + b;
}
__device__ __forceinline__ void unpack2(u64 v, float& a, float& b) {
    asm("mov.b64 {%0, %1}, %2;" : "=f"(a), "=f"(b) : "l"(v));
}
__device__ __forceinline__ uint32_t s2u(const void* p) {
    uint32_t a;
    asm("{ .reg .u64 t; cvta.to.shared.u64 t, %1; cvt.u32.u64 %0, t; }"
        : "=r"(a) : "l"(p));
    return a;
}
__device__ __forceinline__ void mbar_wait0(uint32_t mbar) {
    asm volatile(
        "{\n\t.reg .pred P;\n\t"
        "W%=:\n\t"
        "mbarrier.try_wait.parity.shared.b64 P, [%0], 0;\n\t"
        "@P bra.uni D%=;\n\t"
        "bra.uni W%=;\n\t"
        "D%=:\n\t}"
        :: "r"(mbar) : "memory");
}
__device__ __forceinline__ void tma_load2d(uint32_t dst, const CUtensorMap* m,
                                           int cx, int cy, uint32_t mbar) {
    asm volatile(
        "cp.async.bulk.tensor.2d.shared::cta.global.tile.mbarrier::complete_tx::bytes "
        "[%0], [%1, {%2, %3}], [%4];"
        :: "r"(dst), "l"(m), "r"(cx), "r"(cy), "r"(mbar) : "memory");
}
__device__ __forceinline__ void tma_store2d(const CUtensorMap* m, int cx, int cy,
                                            uint32_t src) {
    asm volatile(
        "cp.async.bulk.tensor.2d.global.shared::cta.tile.bulk_group "
        "[%0, {%1, %2}], [%3];"
        :: "l"(m), "r"(cx), "r"(cy), "r"(src) : "memory");
}

#define T0W 100
#define T1W 140
#define SX0_OFF 5376
#define SX1_OFF (SX0_OFF + 64 * T0W)      // 11776
#define MBAR_OFF (SX1_OFF + 64 * T1W)     // 20736
#define SMEM_BYTES ((MBAR_OFF + 4) * 4)   // 82960

__global__ __launch_bounds__(256, 2) void eqlin_kernel(
    const __grid_constant__ CUtensorMap mi0,
    const __grid_constant__ CUtensorMap mi1,
    const __grid_constant__ CUtensorMap mo0,
    const __grid_constant__ CUtensorMap mo1,
    const float* __restrict__ w)
{
    extern __shared__ __align__(128) float sm[];
    float* sw  = sm;
    float* sx0 = sm + SX0_OFF;
    float* sx1 = sm + SX1_OFF;
    const uint32_t mbar = s2u(sm + MBAR_OFF);

    const int tid = threadIdx.x;
    const int row0 = blockIdx.x * 64;

    if (tid == 0)
        asm volatile("mbarrier.init.shared.b64 [%0], 1;" :: "r"(mbar) : "memory");
    __syncthreads();
    if (tid == 0) {
        asm volatile("mbarrier.arrive.expect_tx.shared.b64 _, [%0], 61440;"
                     :: "r"(mbar) : "memory");
        tma_load2d(s2u(sx0), &mi0, 0,   row0, mbar);
        tma_load2d(s2u(sx1), &mi1, 100, row0, mbar);
    }

    // ---- stage weights (overlaps TMA) ----
    // seg1 re-laid u-pair-major: sw[p*128 + 2v + j] = w[(2p+j)*64 + v] / 8
    #pragma unroll
    for (int k = 0; k < 16; k++) {
        int idx = tid + k * 256;                 // 0..4095
        int u = idx >> 6, v = idx & 63;
        int dst = ((u >> 1) << 7) + (v << 1) + (u & 1);
        sw[dst] = w[idx] * 0.125f;
    }
    #pragma unroll
    for (int k = 0; k < 5; k++) {                // 4096..5375 plain scaled copy
        int idx = 4096 + tid + k * 256;
        float s = (idx < 5120) ? 0.17677669529663687f : 0.25f;
        sw[idx] = w[idx] * s;
    }
    __syncthreads();
    mbar_wait0(mbar);

    const int warp = tid >> 5, lane = tid & 31;

    // ================= Segment 1: 16r x 32v per warp, K-pair (ZERO movs) ====
    // lane: lv = lane&7 (v0 = 32vh + 4lv), lr = lane>>3; rows 16rg + lr + 4rr
    {
        const int rg = warp >> 1, vh = warp & 1;
        const int lv = lane & 7, lr = lane >> 3;
        const int v0 = 32 * vh + 4 * lv;
        const float* xb = sx0 + (16 * rg + lr) * T0W;

        u64 a00 = 0, a01 = 0, a02 = 0, a03 = 0;   // row lr+0, v0..v0+3
        u64 a10 = 0, a11 = 0, a12 = 0, a13 = 0;   // row lr+4
        u64 a20 = 0, a21 = 0, a22 = 0, a23 = 0;   // row lr+8
        u64 a30 = 0, a31 = 0, a32 = 0, a33 = 0;   // row lr+12

        #pragma unroll 2
        for (int k4 = 0; k4 < 16; k4++) {
            // w pairs: p = 2k4, 2k4+1; each ulonglong2 = pairs for (v, v+1)
            const float* wb = sw + k4 * 256 + v0 * 2;
            ulonglong2 W0 = *(const ulonglong2*)(wb);          // p=2k4,  v0,v0+1
            ulonglong2 W0b = *(const ulonglong2*)(wb + 4);     // p=2k4,  v0+2,+3
            ulonglong2 W1 = *(const ulonglong2*)(wb + 128);    // p=2k4+1
            ulonglong2 W1b = *(const ulonglong2*)(wb + 132);
            ulonglong2 x0 = *(const ulonglong2*)(xb + 0 * 4 * T0W + 4 * k4);
            ulonglong2 x1 = *(const ulonglong2*)(xb + 1 * 4 * T0W + 4 * k4);
            ulonglong2 x2 = *(const ulonglong2*)(xb + 2 * 4 * T0W + 4 * k4);
            ulonglong2 x3 = *(const ulonglong2*)(xb + 3 * 4 * T0W + 4 * k4);
            a00 = fma2(x0.y, W1.x,  fma2(x0.x, W0.x,  a00));
            a01 = fma2(x0.y, W1.y,  fma2(x0.x, W0.y,  a01));
            a02 = fma2(x0.y, W1b.x, fma2(x0.x, W0b.x, a02));
            a03 = fma2(x0.y, W1b.y, fma2(x0.x, W0b.y, a03));
            a10 = fma2(x1.y, W1.x,  fma2(x1.x, W0.x,  a10));
            a11 = fma2(x1.y, W1.y,  fma2(x1.x, W0.y,  a11));
            a12 = fma2(x1.y, W1b.x, fma2(x1.x, W0b.x, a12));
            a13 = fma2(x1.y, W1b.y, fma2(x1.x, W0b.y, a13));
            a20 = fma2(x2.y, W1.x,  fma2(x2.x, W0.x,  a20));
            a21 = fma2(x2.y, W1.y,  fma2(x2.x, W0.y,  a21));
            a22 = fma2(x2.y, W1b.x, fma2(x2.x, W0b.x, a22));
            a23 = fma2(x2.y, W1b.y, fma2(x2.x, W0b.y, a23));
            a30 = fma2(x3.y, W1.x,  fma2(x3.x, W0.x,  a30));
            a31 = fma2(x3.y, W1.y,  fma2(x3.x, W0.y,  a31));
            a32 = fma2(x3.y, W1b.x, fma2(x3.x, W0b.x, a32));
            a33 = fma2(x3.y, W1b.y, fma2(x3.x, W0b.y, a33));
        }
        __syncthreads();   // all seg1 reads (cols 0-63) done everywhere
        float* pb = sx0 + (16 * rg + lr) * T0W + v0;
        *(float4*)(pb + 0 * 4 * T0W) =
            make_float4(hsum2(a00), hsum2(a01), hsum2(a02), hsum2(a03));
        *(float4*)(pb + 1 * 4 * T0W) =
            make_float4(hsum2(a10), hsum2(a11), hsum2(a12), hsum2(a13));
        *(float4*)(pb + 2 * 4 * T0W) =
            make_float4(hsum2(a20), hsum2(a21), hsum2(a22), hsum2(a23));
        *(float4*)(pb + 3 * 4 * T0W) =
            make_float4(hsum2(a30), hsum2(a31), hsum2(a32), hsum2(a33));
    }

    // ================= Segment 2: i-pair, hoisted w-dups ====================
    // ty = tid>>4 (rows ty+16s), tx = tid&15 (v-pair va=2tx, vb=2tx+1)
    {
        const int ty = tid >> 4, tx = tid & 15;
        const u64* w2p = (const u64*)(sw + 4096);
        // per (s, v): A01 (i0,i1 pairs, even u), B12 (i1,i2 pairs, odd u),
        //             C2 (scalar i2, even u),    D0 (scalar i0, odd u)
        u64 A01a[4], B12a[4], A01b[4], B12b[4];
        float C2a[4], D0a[4], C2b[4], D0b[4];
        #pragma unroll
        for (int s = 0; s < 4; s++) {
            A01a[s] = 0; B12a[s] = 0; A01b[s] = 0; B12b[s] = 0;
            C2a[s] = 0.f; D0a[s] = 0.f; C2b[s] = 0.f; D0b[s] = 0.f;
        }

        #pragma unroll
        for (int k4 = 0; k4 < 8; k4++) {        // u = 4k4..4k4+3
            u64 wp0 = w2p[(4 * k4 + 0) * 16 + tx];
            u64 wp1 = w2p[(4 * k4 + 1) * 16 + tx];
            u64 wp2 = w2p[(4 * k4 + 2) * 16 + tx];
            u64 wp3 = w2p[(4 * k4 + 3) * 16 + tx];
            float wa0, wb0, wa1, wb1, wa2, wb2, wa3, wb3;
            unpack2(wp0, wa0, wb0); unpack2(wp1, wa1, wb1);
            unpack2(wp2, wa2, wb2); unpack2(wp3, wa3, wb3);
            u64 da0 = dup2(wa0), da1 = dup2(wa1), da2 = dup2(wa2), da3 = dup2(wa3);
            u64 db0 = dup2(wb0), db1 = dup2(wb1), db2 = dup2(wb2), db3 = dup2(wb3);
            #pragma unroll
            for (int s = 0; s < 4; s++) {
                const int row = ty + 16 * s;
                const float* b = (k4 < 3) ? (sx0 + row * T0W + 64 + 12 * k4)
                                          : (sx1 + row * T1W + 12 * k4 - 36);
                ulonglong2 L0 = *(const ulonglong2*)(b);      // (f0f1, f2f3)
                ulonglong2 L1 = *(const ulonglong2*)(b + 4);  // (f4f5, f6f7)
                ulonglong2 L2 = *(const ulonglong2*)(b + 8);  // (f8f9, f10f11)
                float x2, x3, x8, x9;
                unpack2(L0.y, x2, x3);   // u0 i2, u1 i0
                unpack2(L2.x, x8, x9);   // u2 i2, u3 i0
                // u0 (even): pair L0.x = (i0,i1), scalar x2 = i2
                A01a[s] = fma2(L0.x, da0, A01a[s]);  C2a[s] = fmaf(x2, wa0, C2a[s]);
                A01b[s] = fma2(L0.x, db0, A01b[s]);  C2b[s] = fmaf(x2, wb0, C2b[s]);
                // u1 (odd): scalar x3 = i0, pair L1.x = (i1,i2)
                D0a[s] = fmaf(x3, wa1, D0a[s]);  B12a[s] = fma2(L1.x, da1, B12a[s]);
                D0b[s] = fmaf(x3, wb1, D0b[s]);  B12b[s] = fma2(L1.x, db1, B12b[s]);
                // u2 (even): pair L1.y = (i0,i1), scalar x8 = i2
                A01a[s] = fma2(L1.y, da2, A01a[s]);  C2a[s] = fmaf(x8, wa2, C2a[s]);
                A01b[s] = fma2(L1.y, db2, A01b[s]);  C2b[s] = fmaf(x8, wb2, C2b[s]);
                // u3 (odd): scalar x9 = i0, pair L2.y = (i1,i2)
                D0a[s] = fmaf(x9, wa3, D0a[s]);  B12a[s] = fma2(L2.y, da3, B12a[s]);
                D0b[s] = fmaf(x9, wb3, D0b[s]);  B12b[s] = fma2(L2.y, db3, B12b[s]);
            }
        }
        __syncthreads();   // all seg2 reads (cols 64-159) done everywhere
        #pragma unroll
        for (int s = 0; s < 4; s++) {
            const int row = ty + 16 * s;
            float* p = (tx < 6) ? (sx0 + row * T0W + 64 + 6 * tx)
                                : (sx1 + row * T1W + 6 * tx - 36);
            float a0p, a1p, b1p, b2p;
            unpack2(A01a[s], a0p, a1p);
            unpack2(B12a[s], b1p, b2p);
            float va0 = a0p + D0a[s], va1 = a1p + b1p, va2 = b2p + C2a[s];
            unpack2(A01b[s], a0p, a1p);
            unpack2(B12b[s], b1p, b2p);
            float vb0 = a0p + D0b[s], vb1 = a1p + b1p, vb2 = b2p + C2b[s];
            *(float2*)(p)     = make_float2(va0, va1);
            *(float2*)(p + 2) = make_float2(va2, vb0);
            *(float2*)(p + 4) = make_float2(vb1, vb2);
        }
    }

    // ================= Segment 3: 8r x 16v per warp, v-pairs (unchanged) ====
    {
        const int lv3 = lane & 7, lr3 = lane >> 3;
        const int rbase = 8 * warp + lr3;
        const u64* w3q = (const u64*)(sw + 5120);
        u64 cA0 = 0, cA1 = 0, cA2 = 0, cA3 = 0, cA4 = 0;
        u64 cB0 = 0, cB1 = 0, cB2 = 0, cB3 = 0, cB4 = 0;

        #pragma unroll
        for (int k4 = 0; k4 < 4; k4++) {
            const float* pa = sx1 + rbase * T1W + 60 + 20 * k4;
            const float* pb = pa + 4 * T1W;
            float4 qa0 = *(const float4*)(pa);
            float4 qa1 = *(const float4*)(pa + 4);
            float4 qa2 = *(const float4*)(pa + 8);
            float4 qa3 = *(const float4*)(pa + 12);
            float4 qa4 = *(const float4*)(pa + 16);
            float4 qb0 = *(const float4*)(pb);
            float4 qb1 = *(const float4*)(pb + 4);
            float4 qb2 = *(const float4*)(pb + 8);
            float4 qb3 = *(const float4*)(pb + 12);
            float4 qb4 = *(const float4*)(pb + 16);
            u64 wu0 = w3q[(4 * k4 + 0) * 8 + lv3];
            u64 wu1 = w3q[(4 * k4 + 1) * 8 + lv3];
            u64 wu2 = w3q[(4 * k4 + 2) * 8 + lv3];
            u64 wu3 = w3q[(4 * k4 + 3) * 8 + lv3];
            cA0 = fma2(dup2(qa0.x), wu0, cA0);  cB0 = fma2(dup2(qb0.x), wu0, cB0);
            cA1 = fma2(dup2(qa0.y), wu0, cA1);  cB1 = fma2(dup2(qb0.y), wu0, cB1);
            cA2 = fma2(dup2(qa0.z), wu0, cA2);  cB2 = fma2(dup2(qb0.z), wu0, cB2);
            cA3 = fma2(dup2(qa0.w), wu0, cA3);  cB3 = fma2(dup2(qb0.w), wu0, cB3);
            cA4 = fma2(dup2(qa1.x), wu0, cA4);  cB4 = fma2(dup2(qb1.x), wu0, cB4);
            cA0 = fma2(dup2(qa1.y), wu1, cA0);  cB0 = fma2(dup2(qb1.y), wu1, cB0);
            cA1 = fma2(dup2(qa1.z), wu1, cA1);  cB1 = fma2(dup2(qb1.z), wu1, cB1);
            cA2 = fma2(dup2(qa1.w), wu1, cA2);  cB2 = fma2(dup2(qb1.w), wu1, cB2);
            cA3 = fma2(dup2(qa2.x), wu1, cA3);  cB3 = fma2(dup2(qb2.x), wu1, cB3);
            cA4 = fma2(dup2(qa2.y), wu1, cA4);  cB4 = fma2(dup2(qb2.y), wu1, cB4);
            cA0 = fma2(dup2(qa2.z), wu2, cA0);  cB0 = fma2(dup2(qb2.z), wu2, cB0);
            cA1 = fma2(dup2(qa2.w), wu2, cA1);  cB1 = fma2(dup2(qb2.w), wu2, cB1);
            cA2 = fma2(dup2(qa3.x), wu2, cA2);  cB2 = fma2(dup2(qb3.x), wu2, cB2);
            cA3 = fma2(dup2(qa3.y), wu2, cA3);  cB3 = fma2(dup2(qb3.y), wu2, cB3);
            cA4 = fma2(dup2(qa3.z), wu2, cA4);  cB4 = fma2(dup2(qb3.z), wu2, cB4);
            cA0 = fma2(dup2(qa3.w), wu3, cA0);  cB0 = fma2(dup2(qb3.w), wu3, cB0);
            cA1 = fma2(dup2(qa4.x), wu3, cA1);  cB1 = fma2(dup2(qb4.x), wu3, cB1);
            cA2 = fma2(dup2(qa4.y), wu3, cA2);  cB2 = fma2(dup2(qb4.y), wu3, cB2);
            cA3 = fma2(dup2(qa4.z), wu3, cA3);  cB3 = fma2(dup2(qb4.z), wu3, cB3);
            cA4 = fma2(dup2(qa4.w), wu3, cA4);  cB4 = fma2(dup2(qb4.w), wu3, cB4);
        }
        __syncthreads();   // all seg3 reads done everywhere
        float* pA = sx1 + rbase * T1W + 60 + 10 * lv3;
        float* pB = pA + 4 * T1W;
        float l0, h0, l1, h1, l2, h2, l3, h3, l4, h4;
        unpack2(cA0, l0, h0); unpack2(cA1, l1, h1); unpack2(cA2, l2, h2);
        unpack2(cA3, l3, h3); unpack2(cA4, l4, h4);
        *(float2*)(pA)     = make_float2(l0, l1);
        *(float2*)(pA + 2) = make_float2(l2, l3);
        *(float2*)(pA + 4) = make_float2(l4, h0);
        *(float2*)(pA + 6) = make_float2(h1, h2);
        *(float2*)(pA + 8) = make_float2(h3, h4);
        unpack2(cB0, l0, h0); unpack2(cB1, l1, h1); unpack2(cB2, l2, h2);
        unpack2(cB3, l3, h3); unpack2(cB4, l4, h4);
        *(float2*)(pB)     = make_float2(l0, l1);
        *(float2*)(pB + 2) = make_float2(l2, l3);
        *(float2*)(pB + 4) = make_float2(l4, h0);
        *(float2*)(pB + 6) = make_float2(h1, h2);
        *(float2*)(pB + 8) = make_float2(h3, h4);
    }

    __syncthreads();
    if (tid == 0) {
        asm volatile("fence.proxy.async;" ::: "memory");
        tma_store2d(&mo0, 0,   row0, s2u(sx0));
        tma_store2d(&mo1, 100, row0, s2u(sx1));
        asm volatile("cp.async.bulk.commit_group;" ::: "memory");
        asm volatile("cp.async.bulk.wait_group 0;" ::: "memory");
    }
}

// ===================== host side =====================

typedef CUresult (*TmapEncodeFn)(
    CUtensorMap*, CUtensorMapDataType, cuuint32_t, void*,
    const cuuint64_t*, const cuuint64_t*, const cuuint32_t*, const cuuint32_t*,
    CUtensorMapInterleave, CUtensorMapSwizzle, CUtensorMapL2promotion,
    CUtensorMapFloatOOBfill);

static void enc_map(TmapEncodeFn f, CUtensorMap* m, void* base, long long n,
                    uint32_t boxw) {
    cuuint64_t dims[2]    = {240, (cuuint64_t)n};
    cuuint64_t strides[1] = {240 * 4};
    cuuint32_t box[2]     = {boxw, 64};
    cuuint32_t es[2]      = {1, 1};
    f(m, CU_TENSOR_MAP_DATA_TYPE_FLOAT32, 2, base, dims, strides, box, es,
      CU_TENSOR_MAP_INTERLEAVE_NONE, CU_TENSOR_MAP_SWIZZLE_NONE,
      CU_TENSOR_MAP_L2_PROMOTION_L2_128B, CU_TENSOR_MAP_FLOAT_OOB_FILL_NONE);
}

extern "C" void kernel_launch(void* const* d_in, const int* in_sizes, int n_in,
                              void* d_out, int out_size) {
    void* x = d_in[0];
    const float* w = (const float*)d_in[1];
    const long long n = in_sizes[0] / 240;          // 200000
    const int blocks = (int)((n + 63) / 64);        // 3125

    void* fp = nullptr;
    cudaDriverEntryPointQueryResult qr;
#if CUDART_VERSION >= 12050
    cudaGetDriverEntryPointByVersion("cuTensorMapEncodeTiled", &fp, 12000,
                                     cudaEnableDefault, &qr);
#else
    cudaGetDriverEntryPoint("cuTensorMapEncodeTiled", &fp, cudaEnableDefault, &qr);
#endif
    TmapEncodeFn enc = (TmapEncodeFn)fp;

    CUtensorMap mi0, mi1, mo0, mo1;
    enc_map(enc, &mi0, x, n, 100);
    enc_map(enc, &mi1, x, n, 140);
    enc_map(enc, &mo0, d_out, n, 100);
    enc_map(enc, &mo1, d_out, n, 140);

    static bool attr_set = false;
    if (!attr_set) {
        cudaFuncSetAttribute(eqlin_kernel,
                             cudaFuncAttributeMaxDynamicSharedMemorySize, SMEM_BYTES);
        attr_set = true;
    }
    eqlin_kernel<<<blocks, 256, SMEM_BYTES>>>(mi0, mi1, mo0, mo1, w);
}